// round 11
// baseline (speedup 1.0000x reference)
#include <cuda_runtime.h>
#include <cuda_bf16.h>
#include <stdint.h>

// Problem dims (fixed)
#define N_NODES 20000
#define F_IN    8710
#define K_PAD   8768          // 274 * 32
#define HID     1024
#define C_OUT   70
#define E_MAX   320000
#define K2CAT   3072          // [hi | hi | lo] x 1024

// GEMM tiling
#define BM 128
#define BN 128
#define BK 32
#define APAD 40               // smem row stride (80B, 16B aligned, conflict-free)

// ---------------- scratch ----------------------------------------------------
__device__ float g_dinv[N_NODES];
__device__ int   g_cnt [N_NODES];
__device__ int   g_cur [N_NODES];
__device__ int   g_rowptr[N_NODES + 1];
__device__ int   g_csrc[E_MAX];
__device__ __nv_bfloat16 g_w1t[(size_t)HID * K_PAD];      // W1^T bf16
__device__ __nv_bfloat16 g_a1c[(size_t)N_NODES * K2CAT];  // a1 split: [hi|hi|lo]
__device__ __nv_bfloat16 g_w2c[(size_t)128 * K2CAT];      // W2^T cat: [Whi;Wlo;Whi]
__device__ float g_h1  [(size_t)N_NODES * HID];
__device__ float g_h2p [(size_t)N_NODES * 128];           // gemm2 out, padded to 128
__device__ int   g_edges[2 * E_MAX];
__device__ int   g_is64;

__device__ __forceinline__ uint32_t smem_u32(const void* p) {
    uint32_t a;
    asm("{ .reg .u64 t; cvta.to.shared.u64 t, %1; cvt.u32.u64 %0, t; }" : "=r"(a) : "l"(p));
    return a;
}

// ---------------- edge dtype detection + normalization ----------------------
__global__ void detect_edges_k(const void* edges) {
    const long long* p = (const long long*)edges;
    int valid = 0;
    for (int i = 0; i < 256; i++) {
        long long v = p[i];
        if (v >= 0 && v < N_NODES) valid++;
    }
    g_is64 = (valid >= 200) ? 1 : 0;
}
__global__ void conv_edges_k(const void* edges, int total) {
    int i = blockIdx.x * blockDim.x + threadIdx.x;
    if (i >= total) return;
    long long v = g_is64 ? ((const long long*)edges)[i]
                         : (long long)((const int*)edges)[i];
    g_edges[i] = (int)v;
}

// ---------------- CSR build ---------------------------------------------------
__global__ void init0_k(int n) {
    int i = blockIdx.x * blockDim.x + threadIdx.x;
    if (i < n) { g_cnt[i] = 0; g_cur[i] = 0; }
}
__global__ void cnt_k(int E) {
    int e = blockIdx.x * blockDim.x + threadIdx.x;
    if (e < E) atomicAdd(&g_cnt[g_edges[E + e]], 1);
}
__global__ void scan_dinv_k() {
    __shared__ int part[512];
    const int t = threadIdx.x;
    const int CH = (N_NODES + 511) / 512;   // 40
    const int base = t * CH;
    int sum = 0;
    for (int j = 0; j < CH; j++) {
        int n = base + j;
        if (n < N_NODES) sum += g_cnt[n];
    }
    part[t] = sum;
    __syncthreads();
    for (int off = 1; off < 512; off <<= 1) {
        int v = (t >= off) ? part[t - off] : 0;
        __syncthreads();
        part[t] += v;
        __syncthreads();
    }
    int run = (t > 0) ? part[t - 1] : 0;
    for (int j = 0; j < CH; j++) {
        int n = base + j;
        if (n < N_NODES) {
            g_rowptr[n] = run;
            int c = g_cnt[n];
            run += c;
            g_dinv[n] = rsqrtf((float)(c + 1));
        }
    }
    if (t == 511) g_rowptr[N_NODES] = run;
}
__global__ void scatter_k(int E) {
    int e = blockIdx.x * blockDim.x + threadIdx.x;
    if (e >= E) return;
    int s = g_edges[e];
    int d = g_edges[E + e];
    int pos = g_rowptr[d] + atomicAdd(&g_cur[d], 1);
    g_csrc[pos] = s;
}

// ---------------- conversions -------------------------------------------------
__global__ void conv_w1t_k(const float* __restrict__ W1) {
    __shared__ __nv_bfloat16 t[32][33];
    int k0 = blockIdx.x * 32, n0 = blockIdx.y * 32;
    int tx = threadIdx.x, ty = threadIdx.y;
#pragma unroll
    for (int i = 0; i < 32; i += 8) {
        int k = k0 + ty + i, n = n0 + tx;
        float v = (k < F_IN) ? W1[(size_t)k * HID + n] : 0.f;
        t[ty + i][tx] = __float2bfloat16(v);
    }
    __syncthreads();
#pragma unroll
    for (int i = 0; i < 32; i += 8) {
        int n = n0 + ty + i, k = k0 + tx;
        g_w1t[(size_t)n * K_PAD + k] = t[tx][ty + i];
    }
}
// W2 cat: rows n (0..127), cols kk (0..3071): seg0=Whi, seg1=Wlo, seg2=Whi
__global__ void conv_w2c_k(const float* __restrict__ W2) {
    int idx = blockIdx.x * 256 + threadIdx.x;
    if (idx >= 128 * K2CAT) return;
    int n = idx / K2CAT, kk = idx - n * K2CAT;
    int seg = kk >> 10, k = kk & 1023;
    float w = (n < C_OUT) ? W2[(size_t)k * C_OUT + n] : 0.f;
    __nv_bfloat16 hi = __float2bfloat16(w);
    __nv_bfloat16 v;
    if (seg == 1) v = __float2bfloat16(w - __bfloat162float(hi));  // Wlo
    else          v = hi;                                          // Whi
    g_w2c[(size_t)n * K2CAT + kk] = v;
}

// ---------------- bf16 HMMA GEMM body (device-side pointer binding!) ----------
// NOTE: __device__ globals must NEVER be passed as kernel args from host code —
// on GB300 (ATS) the host-shadow address is silently readable/writable and the
// kernel runs on zeros (R6/R8 failure). Globals are bound in device wrappers.
__device__ __forceinline__ void ldsm_x4(uint32_t* r, uint32_t addr) {
    asm volatile("ldmatrix.sync.aligned.m8n8.x4.shared.b16 {%0,%1,%2,%3}, [%4];"
        : "=r"(r[0]), "=r"(r[1]), "=r"(r[2]), "=r"(r[3]) : "r"(addr));
}
__device__ __forceinline__ void ldsm_x2(uint32_t* r, uint32_t addr) {
    asm volatile("ldmatrix.sync.aligned.m8n8.x2.shared.b16 {%0,%1}, [%2];"
        : "=r"(r[0]), "=r"(r[1]) : "r"(addr));
}
__device__ __forceinline__ void mma16816(float* d, const uint32_t* a, const uint32_t* b) {
    asm volatile(
        "mma.sync.aligned.m16n8k16.row.col.f32.bf16.bf16.f32 "
        "{%0,%1,%2,%3}, {%4,%5,%6,%7}, {%8,%9}, {%0,%1,%2,%3};"
        : "+f"(d[0]), "+f"(d[1]), "+f"(d[2]), "+f"(d[3])
        : "r"(a[0]), "r"(a[1]), "r"(a[2]), "r"(a[3]), "r"(b[0]), "r"(b[1]));
}
#define CP_ASYNC16(dst, src) \
    asm volatile("cp.async.cg.shared.global [%0], [%1], 16;" :: "r"(dst), "l"(src))
#define CP_COMMIT() asm volatile("cp.async.commit_group;" ::: "memory")
#define CP_WAIT0()  asm volatile("cp.async.wait_group 0;" ::: "memory")

// Load 8 fp32 from row pointer p at global-k kglob, convert to 8 bf16 packed.
// Guards k >= F_IN without touching OOB memory (x rows are 8B-aligned only).
__device__ __forceinline__ uint4 loadA_cvt(const float* p, int kglob) {
    float v[8];
    if (kglob + 8 <= F_IN) {
        float2 a = *(const float2*)(p + 0);
        float2 b = *(const float2*)(p + 2);
        float2 c = *(const float2*)(p + 4);
        float2 d = *(const float2*)(p + 6);
        v[0] = a.x; v[1] = a.y; v[2] = b.x; v[3] = b.y;
        v[4] = c.x; v[5] = c.y; v[6] = d.x; v[7] = d.y;
    } else {
#pragma unroll
        for (int j = 0; j < 8; j++) v[j] = (kglob + j < F_IN) ? p[j] : 0.f;
    }
    __nv_bfloat162 p0 = __floats2bfloat162_rn(v[0], v[1]);
    __nv_bfloat162 p1 = __floats2bfloat162_rn(v[2], v[3]);
    __nv_bfloat162 p2 = __floats2bfloat162_rn(v[4], v[5]);
    __nv_bfloat162 p3 = __floats2bfloat162_rn(v[6], v[7]);
    uint4 r;
    r.x = *(uint32_t*)&p0; r.y = *(uint32_t*)&p1;
    r.z = *(uint32_t*)&p2; r.w = *(uint32_t*)&p3;
    return r;
}

// AF32=true: A source is fp32 with row stride akstride (x direct), reg-staged.
// AF32=false: A source is bf16, cp.async path (proven R9).
template<int KT, bool AF32>
__device__ __forceinline__ void gemm_body(
    const void* AsrcV, const __nv_bfloat16* Bsrc,
    int akstride, int bkstride, float* dst, int dstride)
{
    __shared__ __align__(16) __nv_bfloat16 As[2][BM * APAD];
    __shared__ __align__(16) __nv_bfloat16 Bs[2][BN * APAD];

    const int tid  = threadIdx.x;
    const int wid  = tid >> 5, lane = tid & 31;
    const int mBase = blockIdx.y * BM;
    const int nBase = blockIdx.x * BN;
    const int mo = (wid >> 2) * 64;
    const int no = (wid & 3) * 32;

    const int r0 = tid >> 2, c0 = (tid & 3) * 8;
    const int r1 = (tid + 256) >> 2, c1 = c0;
    const int amr0 = (mBase + r0 < N_NODES) ? mBase + r0 : N_NODES - 1;
    const int amr1 = (mBase + r1 < N_NODES) ? mBase + r1 : N_NODES - 1;

    const float* aF0 = (const float*)AsrcV + (size_t)amr0 * akstride;
    const float* aF1 = (const float*)AsrcV + (size_t)amr1 * akstride;
    const __nv_bfloat16* aB0 = (const __nv_bfloat16*)AsrcV + (size_t)amr0 * akstride + c0;
    const __nv_bfloat16* aB1 = (const __nv_bfloat16*)AsrcV + (size_t)amr1 * akstride + c1;
    const __nv_bfloat16* bSrc0 = Bsrc + (size_t)(nBase + r0) * bkstride + c0;
    const __nv_bfloat16* bSrc1 = Bsrc + (size_t)(nBase + r1) * bkstride + c1;

    uint32_t aDst0[2], aDst1[2], bDst0[2], bDst1[2];
#pragma unroll
    for (int s = 0; s < 2; s++) {
        aDst0[s] = smem_u32(&As[s][r0 * APAD + c0]);
        aDst1[s] = smem_u32(&As[s][r1 * APAD + c1]);
        bDst0[s] = smem_u32(&Bs[s][r0 * APAD + c0]);
        bDst1[s] = smem_u32(&Bs[s][r1 * APAD + c1]);
    }

    const int lg = lane >> 3, lr = lane & 7;
    const uint32_t aLdBase[2] = {
        smem_u32(&As[0][(mo + (lg & 1) * 8 + lr) * APAD + (lg >> 1) * 8]),
        smem_u32(&As[1][(mo + (lg & 1) * 8 + lr) * APAD + (lg >> 1) * 8]) };
    const int bl = lane & 15, bg = bl >> 3, br = bl & 7;
    const uint32_t bLdBase[2] = {
        smem_u32(&Bs[0][(no + br) * APAD + bg * 8]),
        smem_u32(&Bs[1][(no + br) * APAD + bg * 8]) };

    float acc[4][4][4];
#pragma unroll
    for (int i = 0; i < 4; i++)
#pragma unroll
        for (int j = 0; j < 4; j++)
#pragma unroll
            for (int q = 0; q < 4; q++) acc[i][j][q] = 0.f;

    uint4 aR0, aR1;
    if (AF32) {
        aR0 = loadA_cvt(aF0 + c0, c0);
        aR1 = loadA_cvt(aF1 + c1, c1);
    } else {
        CP_ASYNC16(aDst0[0], aB0);
        CP_ASYNC16(aDst1[0], aB1);
    }
    CP_ASYNC16(bDst0[0], bSrc0);
    CP_ASYNC16(bDst1[0], bSrc1);
    CP_COMMIT();

    for (int it = 0; it < KT; it++) {
        const int s = it & 1;
        uint4 aN0, aN1;
        if (AF32) {
            // stage-s A was last read at iter it-2 (completed; trailing sync).
            *(uint4*)&As[s][r0 * APAD + c0] = aR0;
            *(uint4*)&As[s][r1 * APAD + c1] = aR1;
            if (it + 1 < KT) {
                const int kg = (it + 1) * BK + c0;
                aN0 = loadA_cvt(aF0 + kg, kg);
                aN1 = loadA_cvt(aF1 + kg, kg);
            }
        }
        CP_WAIT0();
        __syncthreads();
        if (it + 1 < KT) {
            const int ns = s ^ 1;
            const size_t ko = (size_t)(it + 1) * BK;
            if (!AF32) {
                CP_ASYNC16(aDst0[ns], aB0 + ko);
                CP_ASYNC16(aDst1[ns], aB1 + ko);
            }
            CP_ASYNC16(bDst0[ns], bSrc0 + ko);
            CP_ASYNC16(bDst1[ns], bSrc1 + ko);
            CP_COMMIT();
        }
#pragma unroll
        for (int ks = 0; ks < 2; ks++) {
            uint32_t a[4][4], b[4][2];
#pragma unroll
            for (int mi = 0; mi < 4; mi++)
                ldsm_x4(a[mi], aLdBase[s] + (mi * 16 * APAD + ks * 16) * 2);
#pragma unroll
            for (int nj = 0; nj < 4; nj++)
                ldsm_x2(b[nj], bLdBase[s] + (nj * 8 * APAD + ks * 16) * 2);
#pragma unroll
            for (int mi = 0; mi < 4; mi++)
#pragma unroll
                for (int nj = 0; nj < 4; nj++)
                    mma16816(acc[mi][nj], a[mi], b[nj]);
        }
        __syncthreads();
        if (AF32 && it + 1 < KT) { aR0 = aN0; aR1 = aN1; }
    }

    const int erow = lane >> 2, ecol = (lane & 3) * 2;
#pragma unroll
    for (int mi = 0; mi < 4; mi++) {
        const int gr0 = mBase + mo + mi * 16 + erow;
        const int gr1 = gr0 + 8;
#pragma unroll
        for (int nj = 0; nj < 4; nj++) {
            const int gc = nBase + no + nj * 8 + ecol;
            if (gr0 < N_NODES)
                *(float2*)(dst + (size_t)gr0 * dstride + gc) = make_float2(acc[mi][nj][0], acc[mi][nj][1]);
            if (gr1 < N_NODES)
                *(float2*)(dst + (size_t)gr1 * dstride + gc) = make_float2(acc[mi][nj][2], acc[mi][nj][3]);
        }
    }
}

// Thin wrappers: device globals bound IN DEVICE CODE.
__global__ __launch_bounds__(256) void gemm1_k(const float* __restrict__ x) {
    gemm_body<K_PAD / BK, true>(x, g_w1t, F_IN, K_PAD, g_h1, HID);
}
__global__ __launch_bounds__(256) void gemm2_k() {
    gemm_body<K2CAT / BK, false>(g_a1c, g_w2c, K2CAT, K2CAT, g_h2p, 128);
}

// ---------------- threefry (JAX partitionable, key=(0,42)) --------------------
__device__ __forceinline__ uint32_t tf_bits(uint32_t i) {
    const uint32_t ks0 = 0u, ks1 = 42u, ks2 = 0u ^ 42u ^ 0x1BD11BDAu;
    uint32_t x0 = 0u + ks0;
    uint32_t x1 = i + ks1;
#define TF_RND(r) { x0 += x1; x1 = (x1 << (r)) | (x1 >> (32 - (r))); x1 ^= x0; }
    TF_RND(13) TF_RND(15) TF_RND(26) TF_RND(6)   x0 += ks1; x1 += ks2 + 1u;
    TF_RND(17) TF_RND(29) TF_RND(16) TF_RND(24)  x0 += ks2; x1 += ks0 + 2u;
    TF_RND(13) TF_RND(15) TF_RND(26) TF_RND(6)   x0 += ks0; x1 += ks1 + 3u;
    TF_RND(17) TF_RND(29) TF_RND(16) TF_RND(24)  x0 += ks1; x1 += ks2 + 4u;
    TF_RND(13) TF_RND(15) TF_RND(26) TF_RND(6)   x0 += ks2; x1 += ks0 + 5u;
#undef TF_RND
    return x0 ^ x1;
}

// ---------------- fused agg1 + bias + relu + dropout -> split bf16 ------------
__global__ __launch_bounds__(256) void spmm1_k(const float* __restrict__ b1) {
    __shared__ int sidx[512];
    const int d = blockIdx.x;
    const int tid = threadIdx.x;
    const float di = g_dinv[d];
    const int beg = g_rowptr[d], end = g_rowptr[d + 1];

    float4 acc = *(const float4*)(g_h1 + (size_t)d * HID + tid * 4);
    const float dii = di * di;
    acc.x *= dii; acc.y *= dii; acc.z *= dii; acc.w *= dii;
    float4 bv = *(const float4*)(b1 + tid * 4);
    acc.x += bv.x; acc.y += bv.y; acc.z += bv.z; acc.w += bv.w;

    for (int chunk = beg; chunk < end; chunk += 512) {
        int n = min(512, end - chunk);
        __syncthreads();
        if (tid < n)       sidx[tid]       = g_csrc[chunk + tid];
        if (tid + 256 < n) sidx[tid + 256] = g_csrc[chunk + tid + 256];
        __syncthreads();
        for (int i = 0; i < n; i++) {
            int s = sidx[i];
            float w = g_dinv[s] * di;
            float4 v = *(const float4*)(g_h1 + (size_t)s * HID + tid * 4);
            acc.x += v.x * w; acc.y += v.y * w; acc.z += v.z * w; acc.w += v.w * w;
        }
    }

    const uint32_t idx = (uint32_t)d * HID + tid * 4;
    float v[4];
    v[0] = fmaxf(acc.x, 0.f); v[1] = fmaxf(acc.y, 0.f);
    v[2] = fmaxf(acc.z, 0.f); v[3] = fmaxf(acc.w, 0.f);
#pragma unroll
    for (int q = 0; q < 4; q++)
        v[q] = (tf_bits(idx + q) & 0x80000000u) ? 0.f : 2.f * v[q];

    __nv_bfloat16 hi[4], lo[4];
#pragma unroll
    for (int q = 0; q < 4; q++) {
        hi[q] = __float2bfloat16(v[q]);
        lo[q] = __float2bfloat16(v[q] - __bfloat162float(hi[q]));
    }
    uint2 phi, plo;
    {
        __nv_bfloat162 h0 = __nv_bfloat162(hi[0], hi[1]);
        __nv_bfloat162 h1 = __nv_bfloat162(hi[2], hi[3]);
        __nv_bfloat162 l0 = __nv_bfloat162(lo[0], lo[1]);
        __nv_bfloat162 l1 = __nv_bfloat162(lo[2], lo[3]);
        phi.x = *(uint32_t*)&h0; phi.y = *(uint32_t*)&h1;
        plo.x = *(uint32_t*)&l0; plo.y = *(uint32_t*)&l1;
    }
    __nv_bfloat16* row = g_a1c + (size_t)d * K2CAT + tid * 4;
    *(uint2*)(row)        = phi;   // seg 0: hi
    *(uint2*)(row + 1024) = phi;   // seg 1: hi
    *(uint2*)(row + 2048) = plo;   // seg 2: lo
}

// ---------------- fused agg2 + bias + log_softmax (warp per node, CSR) --------
__global__ __launch_bounds__(256) void spmm2_k(const float* __restrict__ b2,
                                               float* __restrict__ out) {
    const int row  = blockIdx.x * 8 + (threadIdx.x >> 5);
    const int lane = threadIdx.x & 31;
    if (row >= N_NODES) return;
    const float di = g_dinv[row];
    const float dii = di * di;
    const int beg = g_rowptr[row], end = g_rowptr[row + 1];

    float acc[3];
#pragma unroll
    for (int q = 0; q < 3; q++) {
        int c = lane + q * 32;
        acc[q] = (c < C_OUT) ? g_h2p[(size_t)row * 128 + c] * dii + b2[c] : 0.f;
    }
    for (int i = beg; i < end; i++) {
        int s = g_csrc[i];
        float w = g_dinv[s] * di;
        const float* hs = g_h2p + (size_t)s * 128;
#pragma unroll
        for (int q = 0; q < 3; q++) {
            int c = lane + q * 32;
            if (c < C_OUT) acc[q] += hs[c] * w;
        }
    }
    float m = -1e30f;
#pragma unroll
    for (int q = 0; q < 3; q++) {
        int c = lane + q * 32;
        if (c < C_OUT) m = fmaxf(m, acc[q]);
    }
#pragma unroll
    for (int o = 16; o; o >>= 1) m = fmaxf(m, __shfl_xor_sync(0xffffffffu, m, o));
    float sum = 0.f;
#pragma unroll
    for (int q = 0; q < 3; q++) {
        int c = lane + q * 32;
        if (c < C_OUT) sum += expf(acc[q] - m);
    }
#pragma unroll
    for (int o = 16; o; o >>= 1) sum += __shfl_xor_sync(0xffffffffu, sum, o);
    float lse = m + logf(sum);
    float* orow = out + (size_t)row * C_OUT;
#pragma unroll
    for (int q = 0; q < 3; q++) {
        int c = lane + q * 32;
        if (c < C_OUT) orow[c] = acc[q] - lse;
    }
}

// ---------------- launch ---------------------------------------------------------
extern "C" void kernel_launch(void* const* d_in, const int* in_sizes, int n_in,
                              void* d_out, int out_size) {
    const float* x     = (const float*)d_in[0];
    const void*  edges = d_in[1];
    const float* W1    = (const float*)d_in[2];
    const float* b1    = (const float*)d_in[3];
    const float* W2    = (const float*)d_in[4];
    const float* b2    = (const float*)d_in[5];
    float* out = (float*)d_out;

    const int E = in_sizes[1] / 2;
    const int N = N_NODES;

    detect_edges_k<<<1, 1>>>(edges);
    conv_edges_k<<<(2 * E + 255) / 256, 256>>>(edges, 2 * E);

    // CSR build + dinv
    init0_k    <<<(N + 255) / 256, 256>>>(N);
    cnt_k      <<<(E + 255) / 256, 256>>>(E);
    scan_dinv_k<<<1, 512>>>();
    scatter_k  <<<(E + 255) / 256, 256>>>(E);

    // weight conversions
    conv_w1t_k<<<dim3(K_PAD / 32, HID / 32), dim3(32, 8)>>>(W1);
    conv_w2c_k<<<(128 * K2CAT + 255) / 256, 256>>>(W2);

    // layer 1: HMMA GEMM (A direct from fp32 x) -> fused CSR agg/relu/dropout
    gemm1_k<<<dim3(HID / BN, (N + BM - 1) / BM), 256>>>(x);
    spmm1_k<<<N, 256>>>(b1);

    // layer 2: HMMA GEMM (split bf16) -> fused CSR agg/bias/log_softmax
    gemm2_k<<<dim3(1, (N + BM - 1) / BM), 256>>>();
    spmm2_k<<<(N + 7) / 8, 256>>>(b2, out);
}

// round 12
// speedup vs baseline: 1.4749x; 1.4749x over previous
#include <cuda_runtime.h>
#include <cuda_bf16.h>
#include <stdint.h>

// Problem dims (fixed)
#define N_NODES 20000
#define F_IN    8710
#define K_PAD   8768          // 274 * 32
#define HID     1024
#define C_OUT   70
#define E_MAX   320000
#define K2CAT   3072          // [hi | hi | lo] x 1024

// GEMM tiling
#define BM 128
#define BN 128
#define BK 32
#define APAD 40               // smem row stride (80B, 16B aligned, conflict-free)

// ---------------- scratch ----------------------------------------------------
__device__ float g_dinv[N_NODES];
__device__ int   g_cnt [N_NODES];
__device__ int   g_cur [N_NODES];
__device__ int   g_rowptr[N_NODES + 1];
__device__ int   g_csrc[E_MAX];
__device__ __nv_bfloat16 g_xb [(size_t)N_NODES * K_PAD];  // x bf16, K-padded
__device__ __nv_bfloat16 g_w1t[(size_t)HID * K_PAD];      // W1^T bf16
__device__ __nv_bfloat16 g_h1b[(size_t)N_NODES * HID];    // h1 in bf16
__device__ __nv_bfloat16 g_a1c[(size_t)N_NODES * K2CAT];  // a1 split: [hi|hi|lo]
__device__ __nv_bfloat16 g_w2c[(size_t)128 * K2CAT];      // W2^T cat: [Whi;Wlo;Whi]
__device__ float g_h2p [(size_t)N_NODES * 128];           // gemm2 out, padded to 128
__device__ int   g_edges[2 * E_MAX];
__device__ int   g_is64;

__device__ __forceinline__ uint32_t smem_u32(const void* p) {
    uint32_t a;
    asm("{ .reg .u64 t; cvta.to.shared.u64 t, %1; cvt.u32.u64 %0, t; }" : "=r"(a) : "l"(p));
    return a;
}

// ---------------- edge dtype detection + normalization ----------------------
__global__ void detect_edges_k(const void* edges) {
    const long long* p = (const long long*)edges;
    int valid = 0;
    for (int i = 0; i < 256; i++) {
        long long v = p[i];
        if (v >= 0 && v < N_NODES) valid++;
    }
    g_is64 = (valid >= 200) ? 1 : 0;
}
__global__ void conv_edges_k(const void* edges, int total) {
    int i = blockIdx.x * blockDim.x + threadIdx.x;
    if (i >= total) return;
    long long v = g_is64 ? ((const long long*)edges)[i]
                         : (long long)((const int*)edges)[i];
    g_edges[i] = (int)v;
}

// ---------------- CSR build ---------------------------------------------------
__global__ void init0_k(int n) {
    int i = blockIdx.x * blockDim.x + threadIdx.x;
    if (i < n) { g_cnt[i] = 0; g_cur[i] = 0; }
}
__global__ void cnt_k(int E) {
    int e = blockIdx.x * blockDim.x + threadIdx.x;
    if (e < E) atomicAdd(&g_cnt[g_edges[E + e]], 1);
}
__global__ void scan_dinv_k() {
    __shared__ int part[512];
    const int t = threadIdx.x;
    const int CH = (N_NODES + 511) / 512;   // 40
    const int base = t * CH;
    int sum = 0;
    for (int j = 0; j < CH; j++) {
        int n = base + j;
        if (n < N_NODES) sum += g_cnt[n];
    }
    part[t] = sum;
    __syncthreads();
    for (int off = 1; off < 512; off <<= 1) {
        int v = (t >= off) ? part[t - off] : 0;
        __syncthreads();
        part[t] += v;
        __syncthreads();
    }
    int run = (t > 0) ? part[t - 1] : 0;
    for (int j = 0; j < CH; j++) {
        int n = base + j;
        if (n < N_NODES) {
            g_rowptr[n] = run;
            int c = g_cnt[n];
            run += c;
            g_dinv[n] = rsqrtf((float)(c + 1));
        }
    }
    if (t == 511) g_rowptr[N_NODES] = run;
}
__global__ void scatter_k(int E) {
    int e = blockIdx.x * blockDim.x + threadIdx.x;
    if (e >= E) return;
    int s = g_edges[e];
    int d = g_edges[E + e];
    int pos = g_rowptr[d] + atomicAdd(&g_cur[d], 1);
    g_csrc[pos] = s;
}

// ---------------- conversions -------------------------------------------------
// vectorized: 2 elems/thread. F_IN even -> pairs never straddle the k boundary.
__global__ void conv_x_k(const float* __restrict__ x) {
    int k = (blockIdx.x * 256 + threadIdx.x) * 2;
    int r = blockIdx.y;
    if (k >= K_PAD) return;
    __nv_bfloat162 o;
    if (k < F_IN) {
        float2 v = *(const float2*)(x + (size_t)r * F_IN + k);
        o = __floats2bfloat162_rn(v.x, v.y);
    } else {
        o = __floats2bfloat162_rn(0.f, 0.f);
    }
    *(__nv_bfloat162*)(g_xb + (size_t)r * K_PAD + k) = o;
}
__global__ void conv_w1t_k(const float* __restrict__ W1) {
    __shared__ __nv_bfloat16 t[32][33];
    int k0 = blockIdx.x * 32, n0 = blockIdx.y * 32;
    int tx = threadIdx.x, ty = threadIdx.y;
#pragma unroll
    for (int i = 0; i < 32; i += 8) {
        int k = k0 + ty + i, n = n0 + tx;
        float v = (k < F_IN) ? W1[(size_t)k * HID + n] : 0.f;
        t[ty + i][tx] = __float2bfloat16(v);
    }
    __syncthreads();
#pragma unroll
    for (int i = 0; i < 32; i += 8) {
        int n = n0 + ty + i, k = k0 + tx;
        g_w1t[(size_t)n * K_PAD + k] = t[tx][ty + i];
    }
}
// W2 cat: rows n (0..127), cols kk (0..3071): seg0=Whi, seg1=Wlo, seg2=Whi
__global__ void conv_w2c_k(const float* __restrict__ W2) {
    int idx = blockIdx.x * 256 + threadIdx.x;
    if (idx >= 128 * K2CAT) return;
    int n = idx / K2CAT, kk = idx - n * K2CAT;
    int seg = kk >> 10, k = kk & 1023;
    float w = (n < C_OUT) ? W2[(size_t)k * C_OUT + n] : 0.f;
    __nv_bfloat16 hi = __float2bfloat16(w);
    __nv_bfloat16 v;
    if (seg == 1) v = __float2bfloat16(w - __bfloat162float(hi));  // Wlo
    else          v = hi;                                          // Whi
    g_w2c[(size_t)n * K2CAT + kk] = v;
}

// ---------------- bf16 HMMA GEMM body (device-side pointer binding!) ----------
// NOTE: __device__ globals must NEVER be passed as kernel args from host code —
// on GB300 (ATS) the host-shadow address is silently readable/writable and the
// kernel runs on zeros (R6/R8 failure). Globals are bound in device wrappers.
__device__ __forceinline__ void ldsm_x4(uint32_t* r, uint32_t addr) {
    asm volatile("ldmatrix.sync.aligned.m8n8.x4.shared.b16 {%0,%1,%2,%3}, [%4];"
        : "=r"(r[0]), "=r"(r[1]), "=r"(r[2]), "=r"(r[3]) : "r"(addr));
}
__device__ __forceinline__ void ldsm_x2(uint32_t* r, uint32_t addr) {
    asm volatile("ldmatrix.sync.aligned.m8n8.x2.shared.b16 {%0,%1}, [%2];"
        : "=r"(r[0]), "=r"(r[1]) : "r"(addr));
}
__device__ __forceinline__ void mma16816(float* d, const uint32_t* a, const uint32_t* b) {
    asm volatile(
        "mma.sync.aligned.m16n8k16.row.col.f32.bf16.bf16.f32 "
        "{%0,%1,%2,%3}, {%4,%5,%6,%7}, {%8,%9}, {%0,%1,%2,%3};"
        : "+f"(d[0]), "+f"(d[1]), "+f"(d[2]), "+f"(d[3])
        : "r"(a[0]), "r"(a[1]), "r"(a[2]), "r"(a[3]), "r"(b[0]), "r"(b[1]));
}
#define CP_ASYNC16(dst, src) \
    asm volatile("cp.async.cg.shared.global [%0], [%1], 16;" :: "r"(dst), "l"(src))
#define CP_COMMIT() asm volatile("cp.async.commit_group;" ::: "memory")
#define CP_WAIT0()  asm volatile("cp.async.wait_group 0;" ::: "memory")

// OUT_BF16: epilogue converts fp32 acc -> bf16 (for h1); else fp32 stores.
template<int KT, bool OUT_BF16>
__device__ __forceinline__ void gemm_body(
    const __nv_bfloat16* Asrc, const __nv_bfloat16* Bsrc,
    int kstride, void* dstV, int dstride)
{
    __shared__ __align__(16) __nv_bfloat16 As[2][BM * APAD];
    __shared__ __align__(16) __nv_bfloat16 Bs[2][BN * APAD];

    const int tid  = threadIdx.x;
    const int wid  = tid >> 5, lane = tid & 31;
    const int mBase = blockIdx.y * BM;
    const int nBase = blockIdx.x * BN;
    const int mo = (wid >> 2) * 64;
    const int no = (wid & 3) * 32;

    const int r0 = tid >> 2, c0 = (tid & 3) * 8;
    const int r1 = (tid + 256) >> 2, c1 = c0;
    const int amr0 = (mBase + r0 < N_NODES) ? mBase + r0 : N_NODES - 1;
    const int amr1 = (mBase + r1 < N_NODES) ? mBase + r1 : N_NODES - 1;
    const __nv_bfloat16* aSrc0 = Asrc + (size_t)amr0 * kstride + c0;
    const __nv_bfloat16* aSrc1 = Asrc + (size_t)amr1 * kstride + c1;
    const __nv_bfloat16* bSrc0 = Bsrc + (size_t)(nBase + r0) * kstride + c0;
    const __nv_bfloat16* bSrc1 = Bsrc + (size_t)(nBase + r1) * kstride + c1;

    uint32_t aDst0[2], aDst1[2], bDst0[2], bDst1[2];
#pragma unroll
    for (int s = 0; s < 2; s++) {
        aDst0[s] = smem_u32(&As[s][r0 * APAD + c0]);
        aDst1[s] = smem_u32(&As[s][r1 * APAD + c1]);
        bDst0[s] = smem_u32(&Bs[s][r0 * APAD + c0]);
        bDst1[s] = smem_u32(&Bs[s][r1 * APAD + c1]);
    }

    const int lg = lane >> 3, lr = lane & 7;
    const uint32_t aLdBase[2] = {
        smem_u32(&As[0][(mo + (lg & 1) * 8 + lr) * APAD + (lg >> 1) * 8]),
        smem_u32(&As[1][(mo + (lg & 1) * 8 + lr) * APAD + (lg >> 1) * 8]) };
    const int bl = lane & 15, bg = bl >> 3, br = bl & 7;
    const uint32_t bLdBase[2] = {
        smem_u32(&Bs[0][(no + br) * APAD + bg * 8]),
        smem_u32(&Bs[1][(no + br) * APAD + bg * 8]) };

    float acc[4][4][4];
#pragma unroll
    for (int i = 0; i < 4; i++)
#pragma unroll
        for (int j = 0; j < 4; j++)
#pragma unroll
            for (int q = 0; q < 4; q++) acc[i][j][q] = 0.f;

    CP_ASYNC16(aDst0[0], aSrc0);
    CP_ASYNC16(aDst1[0], aSrc1);
    CP_ASYNC16(bDst0[0], bSrc0);
    CP_ASYNC16(bDst1[0], bSrc1);
    CP_COMMIT();

    for (int it = 0; it < KT; it++) {
        const int s = it & 1;
        CP_WAIT0();
        __syncthreads();
        if (it + 1 < KT) {
            const int ns = s ^ 1;
            const size_t ko = (size_t)(it + 1) * BK;
            CP_ASYNC16(aDst0[ns], aSrc0 + ko);
            CP_ASYNC16(aDst1[ns], aSrc1 + ko);
            CP_ASYNC16(bDst0[ns], bSrc0 + ko);
            CP_ASYNC16(bDst1[ns], bSrc1 + ko);
            CP_COMMIT();
        }
#pragma unroll
        for (int ks = 0; ks < 2; ks++) {
            uint32_t a[4][4], b[4][2];
#pragma unroll
            for (int mi = 0; mi < 4; mi++)
                ldsm_x4(a[mi], aLdBase[s] + (mi * 16 * APAD + ks * 16) * 2);
#pragma unroll
            for (int nj = 0; nj < 4; nj++)
                ldsm_x2(b[nj], bLdBase[s] + (nj * 8 * APAD + ks * 16) * 2);
#pragma unroll
            for (int mi = 0; mi < 4; mi++)
#pragma unroll
                for (int nj = 0; nj < 4; nj++)
                    mma16816(acc[mi][nj], a[mi], b[nj]);
        }
        __syncthreads();
    }

    const int erow = lane >> 2, ecol = (lane & 3) * 2;
#pragma unroll
    for (int mi = 0; mi < 4; mi++) {
        const int gr0 = mBase + mo + mi * 16 + erow;
        const int gr1 = gr0 + 8;
#pragma unroll
        for (int nj = 0; nj < 4; nj++) {
            const int gc = nBase + no + nj * 8 + ecol;
            if (OUT_BF16) {
                __nv_bfloat16* dst = (__nv_bfloat16*)dstV;
                if (gr0 < N_NODES)
                    *(__nv_bfloat162*)(dst + (size_t)gr0 * dstride + gc) =
                        __floats2bfloat162_rn(acc[mi][nj][0], acc[mi][nj][1]);
                if (gr1 < N_NODES)
                    *(__nv_bfloat162*)(dst + (size_t)gr1 * dstride + gc) =
                        __floats2bfloat162_rn(acc[mi][nj][2], acc[mi][nj][3]);
            } else {
                float* dst = (float*)dstV;
                if (gr0 < N_NODES)
                    *(float2*)(dst + (size_t)gr0 * dstride + gc) = make_float2(acc[mi][nj][0], acc[mi][nj][1]);
                if (gr1 < N_NODES)
                    *(float2*)(dst + (size_t)gr1 * dstride + gc) = make_float2(acc[mi][nj][2], acc[mi][nj][3]);
            }
        }
    }
}

// Thin wrappers: device globals bound IN DEVICE CODE.
__global__ __launch_bounds__(256) void gemm1_k() {
    gemm_body<K_PAD / BK, true>(g_xb, g_w1t, K_PAD, g_h1b, HID);
}
__global__ __launch_bounds__(256) void gemm2_k() {
    gemm_body<K2CAT / BK, false>(g_a1c, g_w2c, K2CAT, g_h2p, 128);
}

// ---------------- threefry (JAX partitionable, key=(0,42)) --------------------
__device__ __forceinline__ uint32_t tf_bits(uint32_t i) {
    const uint32_t ks0 = 0u, ks1 = 42u, ks2 = 0u ^ 42u ^ 0x1BD11BDAu;
    uint32_t x0 = 0u + ks0;
    uint32_t x1 = i + ks1;
#define TF_RND(r) { x0 += x1; x1 = (x1 << (r)) | (x1 >> (32 - (r))); x1 ^= x0; }
    TF_RND(13) TF_RND(15) TF_RND(26) TF_RND(6)   x0 += ks1; x1 += ks2 + 1u;
    TF_RND(17) TF_RND(29) TF_RND(16) TF_RND(24)  x0 += ks2; x1 += ks0 + 2u;
    TF_RND(13) TF_RND(15) TF_RND(26) TF_RND(6)   x0 += ks0; x1 += ks1 + 3u;
    TF_RND(17) TF_RND(29) TF_RND(16) TF_RND(24)  x0 += ks1; x1 += ks2 + 4u;
    TF_RND(13) TF_RND(15) TF_RND(26) TF_RND(6)   x0 += ks2; x1 += ks0 + 5u;
#undef TF_RND
    return x0 ^ x1;
}

// ---------------- fused agg1 + bias + relu + dropout -> split bf16 ------------
// one block per dst node; 256 threads x 4 cols. h1 is bf16 (uint2 = 4 vals).
__global__ __launch_bounds__(256) void spmm1_k(const float* __restrict__ b1) {
    __shared__ int sidx[512];
    const int d = blockIdx.x;
    const int tid = threadIdx.x;
    const float di = g_dinv[d];
    const int beg = g_rowptr[d], end = g_rowptr[d + 1];

    float acc[4];
    {
        uint2 p = *(const uint2*)(g_h1b + (size_t)d * HID + tid * 4);
        __nv_bfloat162 q0 = *(__nv_bfloat162*)&p.x;
        __nv_bfloat162 q1 = *(__nv_bfloat162*)&p.y;
        const float dii = di * di;
        float4 bv = *(const float4*)(b1 + tid * 4);
        acc[0] = __bfloat162float(q0.x) * dii + bv.x;
        acc[1] = __bfloat162float(q0.y) * dii + bv.y;
        acc[2] = __bfloat162float(q1.x) * dii + bv.z;
        acc[3] = __bfloat162float(q1.y) * dii + bv.w;
    }

    for (int chunk = beg; chunk < end; chunk += 512) {
        int n = min(512, end - chunk);
        __syncthreads();
        if (tid < n)       sidx[tid]       = g_csrc[chunk + tid];
        if (tid + 256 < n) sidx[tid + 256] = g_csrc[chunk + tid + 256];
        __syncthreads();
        for (int i = 0; i < n; i++) {
            int s = sidx[i];
            float w = g_dinv[s] * di;
            uint2 p = *(const uint2*)(g_h1b + (size_t)s * HID + tid * 4);
            __nv_bfloat162 q0 = *(__nv_bfloat162*)&p.x;
            __nv_bfloat162 q1 = *(__nv_bfloat162*)&p.y;
            acc[0] += __bfloat162float(q0.x) * w;
            acc[1] += __bfloat162float(q0.y) * w;
            acc[2] += __bfloat162float(q1.x) * w;
            acc[3] += __bfloat162float(q1.y) * w;
        }
    }

    const uint32_t idx = (uint32_t)d * HID + tid * 4;
    float v[4];
#pragma unroll
    for (int q = 0; q < 4; q++) {
        v[q] = fmaxf(acc[q], 0.f);
        v[q] = (tf_bits(idx + q) & 0x80000000u) ? 0.f : 2.f * v[q];
    }

    __nv_bfloat16 hi[4], lo[4];
#pragma unroll
    for (int q = 0; q < 4; q++) {
        hi[q] = __float2bfloat16(v[q]);
        lo[q] = __float2bfloat16(v[q] - __bfloat162float(hi[q]));
    }
    uint2 phi, plo;
    {
        __nv_bfloat162 h0 = __nv_bfloat162(hi[0], hi[1]);
        __nv_bfloat162 h1 = __nv_bfloat162(hi[2], hi[3]);
        __nv_bfloat162 l0 = __nv_bfloat162(lo[0], lo[1]);
        __nv_bfloat162 l1 = __nv_bfloat162(lo[2], lo[3]);
        phi.x = *(uint32_t*)&h0; phi.y = *(uint32_t*)&h1;
        plo.x = *(uint32_t*)&l0; plo.y = *(uint32_t*)&l1;
    }
    __nv_bfloat16* row = g_a1c + (size_t)d * K2CAT + tid * 4;
    *(uint2*)(row)        = phi;   // seg 0: hi
    *(uint2*)(row + 1024) = phi;   // seg 1: hi
    *(uint2*)(row + 2048) = plo;   // seg 2: lo
}

// ---------------- fused agg2 + bias + log_softmax (warp per node, CSR) --------
__global__ __launch_bounds__(256) void spmm2_k(const float* __restrict__ b2,
                                               float* __restrict__ out) {
    const int row  = blockIdx.x * 8 + (threadIdx.x >> 5);
    const int lane = threadIdx.x & 31;
    if (row >= N_NODES) return;
    const float di = g_dinv[row];
    const float dii = di * di;
    const int beg = g_rowptr[row], end = g_rowptr[row + 1];

    float acc[3];
#pragma unroll
    for (int q = 0; q < 3; q++) {
        int c = lane + q * 32;
        acc[q] = (c < C_OUT) ? g_h2p[(size_t)row * 128 + c] * dii + b2[c] : 0.f;
    }
    for (int i = beg; i < end; i++) {
        int s = g_csrc[i];
        float w = g_dinv[s] * di;
        const float* hs = g_h2p + (size_t)s * 128;
#pragma unroll
        for (int q = 0; q < 3; q++) {
            int c = lane + q * 32;
            if (c < C_OUT) acc[q] += hs[c] * w;
        }
    }
    float m = -1e30f;
#pragma unroll
    for (int q = 0; q < 3; q++) {
        int c = lane + q * 32;
        if (c < C_OUT) m = fmaxf(m, acc[q]);
    }
#pragma unroll
    for (int o = 16; o; o >>= 1) m = fmaxf(m, __shfl_xor_sync(0xffffffffu, m, o));
    float sum = 0.f;
#pragma unroll
    for (int q = 0; q < 3; q++) {
        int c = lane + q * 32;
        if (c < C_OUT) sum += expf(acc[q] - m);
    }
#pragma unroll
    for (int o = 16; o; o >>= 1) sum += __shfl_xor_sync(0xffffffffu, sum, o);
    float lse = m + logf(sum);
    float* orow = out + (size_t)row * C_OUT;
#pragma unroll
    for (int q = 0; q < 3; q++) {
        int c = lane + q * 32;
        if (c < C_OUT) orow[c] = acc[q] - lse;
    }
}

// ---------------- launch ---------------------------------------------------------
extern "C" void kernel_launch(void* const* d_in, const int* in_sizes, int n_in,
                              void* d_out, int out_size) {
    const float* x     = (const float*)d_in[0];
    const void*  edges = d_in[1];
    const float* W1    = (const float*)d_in[2];
    const float* b1    = (const float*)d_in[3];
    const float* W2    = (const float*)d_in[4];
    const float* b2    = (const float*)d_in[5];
    float* out = (float*)d_out;

    const int E = in_sizes[1] / 2;
    const int N = N_NODES;

    detect_edges_k<<<1, 1>>>(edges);
    conv_edges_k<<<(2 * E + 255) / 256, 256>>>(edges, 2 * E);

    // CSR build + dinv
    init0_k    <<<(N + 255) / 256, 256>>>(N);
    cnt_k      <<<(E + 255) / 256, 256>>>(E);
    scan_dinv_k<<<1, 512>>>();
    scatter_k  <<<(E + 255) / 256, 256>>>(E);

    // bf16 conversions
    conv_x_k  <<<dim3((K_PAD / 2 + 255) / 256, N), 256>>>(x);
    conv_w1t_k<<<dim3(K_PAD / 32, HID / 32), dim3(32, 8)>>>(W1);
    conv_w2c_k<<<(128 * K2CAT + 255) / 256, 256>>>(W2);

    // layer 1: HMMA GEMM (bf16 h1 out) -> fused CSR agg/bias/relu/dropout
    gemm1_k<<<dim3(HID / BN, (N + BM - 1) / BM), 256>>>();
    spmm1_k<<<N, 256>>>(b1);

    // layer 2: HMMA GEMM (split bf16) -> fused CSR agg/bias/log_softmax
    gemm2_k<<<dim3(1, (N + BM - 1) / BM), 256>>>();
    spmm2_k<<<(N + 7) / 8, 256>>>(b2, out);
}

// round 13
// speedup vs baseline: 1.4770x; 1.0015x over previous
#include <cuda_runtime.h>
#include <cuda_bf16.h>
#include <stdint.h>

// Problem dims (fixed)
#define N_NODES 20000
#define F_IN    8710
#define K_PAD   8768          // 274 * 32
#define HID     1024
#define C_OUT   70
#define E_MAX   320000
#define K2CAT   3072          // [hi | hi | lo] x 1024

// GEMM tiling
#define BM 128
#define BN 128
#define BK 32
#define APAD 40               // smem row stride (80B, 16B aligned, conflict-free)

// ---------------- scratch ----------------------------------------------------
__device__ float g_dinv[N_NODES];
__device__ int   g_cnt [N_NODES];
__device__ int   g_cur [N_NODES];
__device__ int   g_rowptr[N_NODES + 1];
__device__ int   g_csrc[E_MAX];
__device__ __nv_bfloat16 g_xb [(size_t)N_NODES * K_PAD];  // x bf16, K-padded
__device__ __nv_bfloat16 g_w1t[(size_t)HID * K_PAD];      // W1^T bf16
__device__ __nv_bfloat16 g_h1b[(size_t)N_NODES * HID];    // h1 in bf16
__device__ __nv_bfloat16 g_a1c[(size_t)N_NODES * K2CAT];  // a1 split: [hi|hi|lo]
__device__ __nv_bfloat16 g_w2c[(size_t)128 * K2CAT];      // W2^T cat: [Whi;Wlo;Whi]
__device__ float g_h2p [(size_t)N_NODES * 128];           // gemm2 out, padded to 128
__device__ int   g_edges[2 * E_MAX];
__device__ int   g_is64;

__device__ __forceinline__ uint32_t smem_u32(const void* p) {
    uint32_t a;
    asm("{ .reg .u64 t; cvta.to.shared.u64 t, %1; cvt.u32.u64 %0, t; }" : "=r"(a) : "l"(p));
    return a;
}

// ---------------- edge dtype detection + normalization ----------------------
__global__ void detect_edges_k(const void* edges) {
    const long long* p = (const long long*)edges;
    int valid = 0;
    for (int i = 0; i < 256; i++) {
        long long v = p[i];
        if (v >= 0 && v < N_NODES) valid++;
    }
    g_is64 = (valid >= 200) ? 1 : 0;
}
__global__ void conv_edges_k(const void* edges, int total) {
    int i = blockIdx.x * blockDim.x + threadIdx.x;
    if (i >= total) return;
    long long v = g_is64 ? ((const long long*)edges)[i]
                         : (long long)((const int*)edges)[i];
    g_edges[i] = (int)v;
}

// ---------------- CSR build ---------------------------------------------------
__global__ void init0_k(int n) {
    int i = blockIdx.x * blockDim.x + threadIdx.x;
    if (i < n) { g_cnt[i] = 0; g_cur[i] = 0; }
}
__global__ void cnt_k(int E) {
    int e = blockIdx.x * blockDim.x + threadIdx.x;
    if (e < E) atomicAdd(&g_cnt[g_edges[E + e]], 1);
}
__global__ void scan_dinv_k() {
    __shared__ int part[512];
    const int t = threadIdx.x;
    const int CH = (N_NODES + 511) / 512;   // 40
    const int base = t * CH;
    int sum = 0;
    for (int j = 0; j < CH; j++) {
        int n = base + j;
        if (n < N_NODES) sum += g_cnt[n];
    }
    part[t] = sum;
    __syncthreads();
    for (int off = 1; off < 512; off <<= 1) {
        int v = (t >= off) ? part[t - off] : 0;
        __syncthreads();
        part[t] += v;
        __syncthreads();
    }
    int run = (t > 0) ? part[t - 1] : 0;
    for (int j = 0; j < CH; j++) {
        int n = base + j;
        if (n < N_NODES) {
            g_rowptr[n] = run;
            int c = g_cnt[n];
            run += c;
            g_dinv[n] = rsqrtf((float)(c + 1));
        }
    }
    if (t == 511) g_rowptr[N_NODES] = run;
}
__global__ void scatter_k(int E) {
    int e = blockIdx.x * blockDim.x + threadIdx.x;
    if (e >= E) return;
    int s = g_edges[e];
    int d = g_edges[E + e];
    int pos = g_rowptr[d] + atomicAdd(&g_cur[d], 1);
    g_csrc[pos] = s;
}

// ---------------- conversions -------------------------------------------------
// vectorized: 2 elems/thread. F_IN even -> pairs never straddle the k boundary.
__global__ void conv_x_k(const float* __restrict__ x) {
    int k = (blockIdx.x * 256 + threadIdx.x) * 2;
    int r = blockIdx.y;
    if (k >= K_PAD) return;
    __nv_bfloat162 o;
    if (k < F_IN) {
        float2 v = *(const float2*)(x + (size_t)r * F_IN + k);
        o = __floats2bfloat162_rn(v.x, v.y);
    } else {
        o = __floats2bfloat162_rn(0.f, 0.f);
    }
    *(__nv_bfloat162*)(g_xb + (size_t)r * K_PAD + k) = o;
}
__global__ void conv_w1t_k(const float* __restrict__ W1) {
    __shared__ __nv_bfloat16 t[32][33];
    int k0 = blockIdx.x * 32, n0 = blockIdx.y * 32;
    int tx = threadIdx.x, ty = threadIdx.y;
#pragma unroll
    for (int i = 0; i < 32; i += 8) {
        int k = k0 + ty + i, n = n0 + tx;
        float v = (k < F_IN) ? W1[(size_t)k * HID + n] : 0.f;
        t[ty + i][tx] = __float2bfloat16(v);
    }
    __syncthreads();
#pragma unroll
    for (int i = 0; i < 32; i += 8) {
        int n = n0 + ty + i, k = k0 + tx;
        g_w1t[(size_t)n * K_PAD + k] = t[tx][ty + i];
    }
}
// W2 cat: rows n (0..127), cols kk (0..3071): seg0=Whi, seg1=Wlo, seg2=Whi
__global__ void conv_w2c_k(const float* __restrict__ W2) {
    int idx = blockIdx.x * 256 + threadIdx.x;
    if (idx >= 128 * K2CAT) return;
    int n = idx / K2CAT, kk = idx - n * K2CAT;
    int seg = kk >> 10, k = kk & 1023;
    float w = (n < C_OUT) ? W2[(size_t)k * C_OUT + n] : 0.f;
    __nv_bfloat16 hi = __float2bfloat16(w);
    __nv_bfloat16 v;
    if (seg == 1) v = __float2bfloat16(w - __bfloat162float(hi));  // Wlo
    else          v = hi;                                          // Whi
    g_w2c[(size_t)n * K2CAT + kk] = v;
}

// ---------------- bf16 HMMA GEMM body (device-side pointer binding!) ----------
// NOTE: __device__ globals must NEVER be passed as kernel args from host code —
// on GB300 (ATS) the host-shadow address is silently readable/writable and the
// kernel runs on zeros (R6/R8 failure). Globals are bound in device wrappers.
__device__ __forceinline__ void ldsm_x4(uint32_t* r, uint32_t addr) {
    asm volatile("ldmatrix.sync.aligned.m8n8.x4.shared.b16 {%0,%1,%2,%3}, [%4];"
        : "=r"(r[0]), "=r"(r[1]), "=r"(r[2]), "=r"(r[3]) : "r"(addr));
}
__device__ __forceinline__ void ldsm_x2(uint32_t* r, uint32_t addr) {
    asm volatile("ldmatrix.sync.aligned.m8n8.x2.shared.b16 {%0,%1}, [%2];"
        : "=r"(r[0]), "=r"(r[1]) : "r"(addr));
}
__device__ __forceinline__ void mma16816(float* d, const uint32_t* a, const uint32_t* b) {
    asm volatile(
        "mma.sync.aligned.m16n8k16.row.col.f32.bf16.bf16.f32 "
        "{%0,%1,%2,%3}, {%4,%5,%6,%7}, {%8,%9}, {%0,%1,%2,%3};"
        : "+f"(d[0]), "+f"(d[1]), "+f"(d[2]), "+f"(d[3])
        : "r"(a[0]), "r"(a[1]), "r"(a[2]), "r"(a[3]), "r"(b[0]), "r"(b[1]));
}
#define CP_ASYNC16(dst, src) \
    asm volatile("cp.async.cg.shared.global [%0], [%1], 16;" :: "r"(dst), "l"(src))
#define CP_COMMIT() asm volatile("cp.async.commit_group;" ::: "memory")
#define CP_WAIT0()  asm volatile("cp.async.wait_group 0;" ::: "memory")

// OUT_BF16: epilogue converts fp32 acc -> bf16 (for h1); else fp32 stores.
template<int KT, bool OUT_BF16>
__device__ __forceinline__ void gemm_body(
    const __nv_bfloat16* Asrc, const __nv_bfloat16* Bsrc,
    int kstride, void* dstV, int dstride)
{
    __shared__ __align__(16) __nv_bfloat16 As[2][BM * APAD];
    __shared__ __align__(16) __nv_bfloat16 Bs[2][BN * APAD];

    const int tid  = threadIdx.x;
    const int wid  = tid >> 5, lane = tid & 31;
    const int mBase = blockIdx.y * BM;
    const int nBase = blockIdx.x * BN;
    const int mo = (wid >> 2) * 64;
    const int no = (wid & 3) * 32;

    const int r0 = tid >> 2, c0 = (tid & 3) * 8;
    const int r1 = (tid + 256) >> 2, c1 = c0;
    const int amr0 = (mBase + r0 < N_NODES) ? mBase + r0 : N_NODES - 1;
    const int amr1 = (mBase + r1 < N_NODES) ? mBase + r1 : N_NODES - 1;
    const __nv_bfloat16* aSrc0 = Asrc + (size_t)amr0 * kstride + c0;
    const __nv_bfloat16* aSrc1 = Asrc + (size_t)amr1 * kstride + c1;
    const __nv_bfloat16* bSrc0 = Bsrc + (size_t)(nBase + r0) * kstride + c0;
    const __nv_bfloat16* bSrc1 = Bsrc + (size_t)(nBase + r1) * kstride + c1;

    uint32_t aDst0[2], aDst1[2], bDst0[2], bDst1[2];
#pragma unroll
    for (int s = 0; s < 2; s++) {
        aDst0[s] = smem_u32(&As[s][r0 * APAD + c0]);
        aDst1[s] = smem_u32(&As[s][r1 * APAD + c1]);
        bDst0[s] = smem_u32(&Bs[s][r0 * APAD + c0]);
        bDst1[s] = smem_u32(&Bs[s][r1 * APAD + c1]);
    }

    const int lg = lane >> 3, lr = lane & 7;
    const uint32_t aLdBase[2] = {
        smem_u32(&As[0][(mo + (lg & 1) * 8 + lr) * APAD + (lg >> 1) * 8]),
        smem_u32(&As[1][(mo + (lg & 1) * 8 + lr) * APAD + (lg >> 1) * 8]) };
    const int bl = lane & 15, bg = bl >> 3, br = bl & 7;
    const uint32_t bLdBase[2] = {
        smem_u32(&Bs[0][(no + br) * APAD + bg * 8]),
        smem_u32(&Bs[1][(no + br) * APAD + bg * 8]) };

    float acc[4][4][4];
#pragma unroll
    for (int i = 0; i < 4; i++)
#pragma unroll
        for (int j = 0; j < 4; j++)
#pragma unroll
            for (int q = 0; q < 4; q++) acc[i][j][q] = 0.f;

    CP_ASYNC16(aDst0[0], aSrc0);
    CP_ASYNC16(aDst1[0], aSrc1);
    CP_ASYNC16(bDst0[0], bSrc0);
    CP_ASYNC16(bDst1[0], bSrc1);
    CP_COMMIT();

    for (int it = 0; it < KT; it++) {
        const int s = it & 1;
        CP_WAIT0();
        __syncthreads();
        if (it + 1 < KT) {
            const int ns = s ^ 1;
            const size_t ko = (size_t)(it + 1) * BK;
            CP_ASYNC16(aDst0[ns], aSrc0 + ko);
            CP_ASYNC16(aDst1[ns], aSrc1 + ko);
            CP_ASYNC16(bDst0[ns], bSrc0 + ko);
            CP_ASYNC16(bDst1[ns], bSrc1 + ko);
            CP_COMMIT();
        }
#pragma unroll
        for (int ks = 0; ks < 2; ks++) {
            uint32_t a[4][4], b[4][2];
#pragma unroll
            for (int mi = 0; mi < 4; mi++)
                ldsm_x4(a[mi], aLdBase[s] + (mi * 16 * APAD + ks * 16) * 2);
#pragma unroll
            for (int nj = 0; nj < 4; nj++)
                ldsm_x2(b[nj], bLdBase[s] + (nj * 8 * APAD + ks * 16) * 2);
#pragma unroll
            for (int mi = 0; mi < 4; mi++)
#pragma unroll
                for (int nj = 0; nj < 4; nj++)
                    mma16816(acc[mi][nj], a[mi], b[nj]);
        }
        __syncthreads();
    }

    const int erow = lane >> 2, ecol = (lane & 3) * 2;
#pragma unroll
    for (int mi = 0; mi < 4; mi++) {
        const int gr0 = mBase + mo + mi * 16 + erow;
        const int gr1 = gr0 + 8;
#pragma unroll
        for (int nj = 0; nj < 4; nj++) {
            const int gc = nBase + no + nj * 8 + ecol;
            if (OUT_BF16) {
                __nv_bfloat16* dst = (__nv_bfloat16*)dstV;
                if (gr0 < N_NODES)
                    *(__nv_bfloat162*)(dst + (size_t)gr0 * dstride + gc) =
                        __floats2bfloat162_rn(acc[mi][nj][0], acc[mi][nj][1]);
                if (gr1 < N_NODES)
                    *(__nv_bfloat162*)(dst + (size_t)gr1 * dstride + gc) =
                        __floats2bfloat162_rn(acc[mi][nj][2], acc[mi][nj][3]);
            } else {
                float* dst = (float*)dstV;
                if (gr0 < N_NODES)
                    *(float2*)(dst + (size_t)gr0 * dstride + gc) = make_float2(acc[mi][nj][0], acc[mi][nj][1]);
                if (gr1 < N_NODES)
                    *(float2*)(dst + (size_t)gr1 * dstride + gc) = make_float2(acc[mi][nj][2], acc[mi][nj][3]);
            }
        }
    }
}

// Thin wrappers: device globals bound IN DEVICE CODE.
// __launch_bounds__(256, 2): cap regs at 128 -> 2 CTAs/SM -> 4 warps/SMSP
// (R11 ran 1 CTA/SM at ~130 regs; tensor issue was only ~50% occupied).
__global__ __launch_bounds__(256, 2) void gemm1_k() {
    gemm_body<K_PAD / BK, true>(g_xb, g_w1t, K_PAD, g_h1b, HID);
}
__global__ __launch_bounds__(256, 2) void gemm2_k() {
    gemm_body<K2CAT / BK, false>(g_a1c, g_w2c, K2CAT, g_h2p, 128);
}

// ---------------- threefry (JAX partitionable, key=(0,42)) --------------------
__device__ __forceinline__ uint32_t tf_bits(uint32_t i) {
    const uint32_t ks0 = 0u, ks1 = 42u, ks2 = 0u ^ 42u ^ 0x1BD11BDAu;
    uint32_t x0 = 0u + ks0;
    uint32_t x1 = i + ks1;
#define TF_RND(r) { x0 += x1; x1 = (x1 << (r)) | (x1 >> (32 - (r))); x1 ^= x0; }
    TF_RND(13) TF_RND(15) TF_RND(26) TF_RND(6)   x0 += ks1; x1 += ks2 + 1u;
    TF_RND(17) TF_RND(29) TF_RND(16) TF_RND(24)  x0 += ks2; x1 += ks0 + 2u;
    TF_RND(13) TF_RND(15) TF_RND(26) TF_RND(6)   x0 += ks0; x1 += ks1 + 3u;
    TF_RND(17) TF_RND(29) TF_RND(16) TF_RND(24)  x0 += ks1; x1 += ks2 + 4u;
    TF_RND(13) TF_RND(15) TF_RND(26) TF_RND(6)   x0 += ks2; x1 += ks0 + 5u;
#undef TF_RND
    return x0 ^ x1;
}

// ---------------- fused agg1 + bias + relu + dropout -> split bf16 ------------
// one block per dst node; 256 threads x 4 cols. h1 is bf16 (uint2 = 4 vals).
__global__ __launch_bounds__(256) void spmm1_k(const float* __restrict__ b1) {
    __shared__ int sidx[512];
    const int d = blockIdx.x;
    const int tid = threadIdx.x;
    const float di = g_dinv[d];
    const int beg = g_rowptr[d], end = g_rowptr[d + 1];

    float acc[4];
    {
        uint2 p = *(const uint2*)(g_h1b + (size_t)d * HID + tid * 4);
        __nv_bfloat162 q0 = *(__nv_bfloat162*)&p.x;
        __nv_bfloat162 q1 = *(__nv_bfloat162*)&p.y;
        const float dii = di * di;
        float4 bv = *(const float4*)(b1 + tid * 4);
        acc[0] = __bfloat162float(q0.x) * dii + bv.x;
        acc[1] = __bfloat162float(q0.y) * dii + bv.y;
        acc[2] = __bfloat162float(q1.x) * dii + bv.z;
        acc[3] = __bfloat162float(q1.y) * dii + bv.w;
    }

    for (int chunk = beg; chunk < end; chunk += 512) {
        int n = min(512, end - chunk);
        __syncthreads();
        if (tid < n)       sidx[tid]       = g_csrc[chunk + tid];
        if (tid + 256 < n) sidx[tid + 256] = g_csrc[chunk + tid + 256];
        __syncthreads();
        for (int i = 0; i < n; i++) {
            int s = sidx[i];
            float w = g_dinv[s] * di;
            uint2 p = *(const uint2*)(g_h1b + (size_t)s * HID + tid * 4);
            __nv_bfloat162 q0 = *(__nv_bfloat162*)&p.x;
            __nv_bfloat162 q1 = *(__nv_bfloat162*)&p.y;
            acc[0] += __bfloat162float(q0.x) * w;
            acc[1] += __bfloat162float(q0.y) * w;
            acc[2] += __bfloat162float(q1.x) * w;
            acc[3] += __bfloat162float(q1.y) * w;
        }
    }

    const uint32_t idx = (uint32_t)d * HID + tid * 4;
    float v[4];
#pragma unroll
    for (int q = 0; q < 4; q++) {
        v[q] = fmaxf(acc[q], 0.f);
        v[q] = (tf_bits(idx + q) & 0x80000000u) ? 0.f : 2.f * v[q];
    }

    __nv_bfloat16 hi[4], lo[4];
#pragma unroll
    for (int q = 0; q < 4; q++) {
        hi[q] = __float2bfloat16(v[q]);
        lo[q] = __float2bfloat16(v[q] - __bfloat162float(hi[q]));
    }
    uint2 phi, plo;
    {
        __nv_bfloat162 h0 = __nv_bfloat162(hi[0], hi[1]);
        __nv_bfloat162 h1 = __nv_bfloat162(hi[2], hi[3]);
        __nv_bfloat162 l0 = __nv_bfloat162(lo[0], lo[1]);
        __nv_bfloat162 l1 = __nv_bfloat162(lo[2], lo[3]);
        phi.x = *(uint32_t*)&h0; phi.y = *(uint32_t*)&h1;
        plo.x = *(uint32_t*)&l0; plo.y = *(uint32_t*)&l1;
    }
    __nv_bfloat16* row = g_a1c + (size_t)d * K2CAT + tid * 4;
    *(uint2*)(row)        = phi;   // seg 0: hi
    *(uint2*)(row + 1024) = phi;   // seg 1: hi
    *(uint2*)(row + 2048) = plo;   // seg 2: lo
}

// ---------------- fused agg2 + bias + log_softmax (warp per node, CSR) --------
__global__ __launch_bounds__(256) void spmm2_k(const float* __restrict__ b2,
                                               float* __restrict__ out) {
    const int row  = blockIdx.x * 8 + (threadIdx.x >> 5);
    const int lane = threadIdx.x & 31;
    if (row >= N_NODES) return;
    const float di = g_dinv[row];
    const float dii = di * di;
    const int beg = g_rowptr[row], end = g_rowptr[row + 1];

    float acc[3];
#pragma unroll
    for (int q = 0; q < 3; q++) {
        int c = lane + q * 32;
        acc[q] = (c < C_OUT) ? g_h2p[(size_t)row * 128 + c] * dii + b2[c] : 0.f;
    }
    for (int i = beg; i < end; i++) {
        int s = g_csrc[i];
        float w = g_dinv[s] * di;
        const float* hs = g_h2p + (size_t)s * 128;
#pragma unroll
        for (int q = 0; q < 3; q++) {
            int c = lane + q * 32;
            if (c < C_OUT) acc[q] += hs[c] * w;
        }
    }
    float m = -1e30f;
#pragma unroll
    for (int q = 0; q < 3; q++) {
        int c = lane + q * 32;
        if (c < C_OUT) m = fmaxf(m, acc[q]);
    }
#pragma unroll
    for (int o = 16; o; o >>= 1) m = fmaxf(m, __shfl_xor_sync(0xffffffffu, m, o));
    float sum = 0.f;
#pragma unroll
    for (int q = 0; q < 3; q++) {
        int c = lane + q * 32;
        if (c < C_OUT) sum += expf(acc[q] - m);
    }
#pragma unroll
    for (int o = 16; o; o >>= 1) sum += __shfl_xor_sync(0xffffffffu, sum, o);
    float lse = m + logf(sum);
    float* orow = out + (size_t)row * C_OUT;
#pragma unroll
    for (int q = 0; q < 3; q++) {
        int c = lane + q * 32;
        if (c < C_OUT) orow[c] = acc[q] - lse;
    }
}

// ---------------- launch ---------------------------------------------------------
extern "C" void kernel_launch(void* const* d_in, const int* in_sizes, int n_in,
                              void* d_out, int out_size) {
    const float* x     = (const float*)d_in[0];
    const void*  edges = d_in[1];
    const float* W1    = (const float*)d_in[2];
    const float* b1    = (const float*)d_in[3];
    const float* W2    = (const float*)d_in[4];
    const float* b2    = (const float*)d_in[5];
    float* out = (float*)d_out;

    const int E = in_sizes[1] / 2;
    const int N = N_NODES;

    detect_edges_k<<<1, 1>>>(edges);
    conv_edges_k<<<(2 * E + 255) / 256, 256>>>(edges, 2 * E);

    // CSR build + dinv
    init0_k    <<<(N + 255) / 256, 256>>>(N);
    cnt_k      <<<(E + 255) / 256, 256>>>(E);
    scan_dinv_k<<<1, 512>>>();
    scatter_k  <<<(E + 255) / 256, 256>>>(E);

    // bf16 conversions
    conv_x_k  <<<dim3((K_PAD / 2 + 255) / 256, N), 256>>>(x);
    conv_w1t_k<<<dim3(K_PAD / 32, HID / 32), dim3(32, 8)>>>(W1);
    conv_w2c_k<<<(128 * K2CAT + 255) / 256, 256>>>(W2);

    // layer 1: HMMA GEMM (bf16 h1 out) -> fused CSR agg/bias/relu/dropout
    gemm1_k<<<dim3(HID / BN, (N + BM - 1) / BM), 256>>>();
    spmm1_k<<<N, 256>>>(b1);

    // layer 2: HMMA GEMM (split bf16) -> fused CSR agg/bias/log_softmax
    gemm2_k<<<dim3(1, (N + BM - 1) / BM), 256>>>();
    spmm2_k<<<(N + 7) / 8, 256>>>(b2, out);
}